// round 16
// baseline (speedup 1.0000x reference)
#include <cuda_runtime.h>

#define KW     512
#define KP     (KW / 2)      // k-pairs total
#define KSPLIT 8
#define KPB    (KP / KSPLIT) // k-pairs per block = 32
#define NPT    4             // points per thread
#define BLK    128           // threads per block

typedef unsigned long long u64;

// Precomputed per-k-pair constant table: KP entries x 7 float4 (28 KB)
__device__ float4 g_kc[KP * 7];

// ---------- packed f32x2 helpers ----------
__device__ __forceinline__ u64 pk2(float lo, float hi) {
    u64 r;
    asm("mov.b64 %0, {%1, %2};" : "=l"(r) : "f"(lo), "f"(hi));
    return r;
}
__device__ __forceinline__ void upk2(u64 v, float& lo, float& hi) {
    asm("mov.b64 {%0, %1}, %2;" : "=f"(lo), "=f"(hi) : "l"(v));
}
__device__ __forceinline__ u64 fma2(u64 a, u64 b, u64 c) {
    u64 d;
    asm("fma.rn.f32x2 %0, %1, %2, %3;" : "=l"(d) : "l"(a), "l"(b), "l"(c));
    return d;
}
__device__ __forceinline__ u64 mul2(u64 a, u64 b) {
    u64 d;
    asm("mul.rn.f32x2 %0, %1, %2;" : "=l"(d) : "l"(a), "l"(b));
    return d;
}
__device__ __forceinline__ u64 add2(u64 a, u64 b) {
    u64 d;
    asm("add.rn.f32x2 %0, %1, %2;" : "=l"(d) : "l"(a), "l"(b));
    return d;
}
__device__ __forceinline__ float ex2f(float a) {
    float r;
    asm("ex2.approx.ftz.f32 %0, %1;" : "=f"(r) : "f"(a));
    return r;
}

// Combined init:
//  blocks [0, nOutBlk): out[0..N) = bias, out[N..4N) = 0 (float4 stores)
//  block  nOutBlk     : build g_kc table (256 threads, one kp entry each)
__global__ __launch_bounds__(256)
void awpinn_init(
    const float* __restrict__ wx, const float* __restrict__ bx,
    const float* __restrict__ wy, const float* __restrict__ by,
    const float* __restrict__ wz, const float* __restrict__ bz,
    const float* __restrict__ coeff, const float* __restrict__ bias,
    float4* __restrict__ out, int N, int nOutBlk)
{
    if ((int)blockIdx.x < nOutBlk) {
        int j = blockIdx.x * 256 + threadIdx.x;    // float4 units over 4N floats
        int total = N;                              // 4N/4
        int row0  = N >> 2;                         // float4 units in row 0
        if (j < total) {
            float b = (j < row0) ? bias[0] : 0.0f;
            out[j] = make_float4(b, b, b, b);
        }
        return;
    }

    // table-build block
    int kpair = threadIdx.x;                        // 0..KP-1 (KP=256)
    if (kpair < KP) {
        int k0 = 2 * kpair, k1 = k0 + 1;
        float wx0 = wx[k0], wx1 = wx[k1];
        float wy0 = wy[k0], wy1 = wy[k1];
        float wz0 = wz[k0], wz1 = wz[k1];
        float c0 = sqrtf(fmaxf(wx0 * wy0 * wz0, 1e-12f)) * coeff[k0];
        float c1 = sqrtf(fmaxf(wx1 * wy1 * wz1, 1e-12f)) * coeff[k1];
        // cp = (-c)*q*exp2(s*C)  ->  sign(-c) XOR ( q * exp2(s*C + log2|c|) )
        float lc0 = __log2f(fabsf(c0));
        float lc1 = __log2f(fabsf(c1));
        unsigned int sg0 = (c0 > 0.0f) ? 0x80000000u : 0u;
        unsigned int sg1 = (c1 > 0.0f) ? 0x80000000u : 0u;
        float wx20 = wx0 * wx0, wx21 = wx1 * wx1;
        float wy20 = wy0 * wy0, wy21 = wy1 * wy1;
        float wz20 = wz0 * wz0, wz21 = wz1 * wz1;
        float4* e = &g_kc[kpair * 7];
        e[0] = make_float4(wx0, wx1, -bx[k0], -bx[k1]);
        e[1] = make_float4(wy0, wy1, -by[k0], -by[k1]);
        e[2] = make_float4(wz0, wz1, -bz[k0], -bz[k1]);
        e[3] = make_float4(lc0, lc1, __uint_as_float(sg0), __uint_as_float(sg1));
        e[4] = make_float4(wx20, wx21, -3.0f * wx20, -3.0f * wx21);
        e[5] = make_float4(wy20, wy21, -3.0f * wy20, -3.0f * wy21);
        e[6] = make_float4(wz20, wz21, -3.0f * wz20, -3.0f * wz21);
    }
}

__global__ __launch_bounds__(BLK, 4)
void awpinn_main(
    const float* __restrict__ x, const float* __restrict__ y, const float* __restrict__ z,
    float* __restrict__ out, int N)
{
    __shared__ float4 kc[KPB * 7];

    const int split = blockIdx.x & (KSPLIT - 1);
    const int pg    = blockIdx.x >> 3;          // point-group index
    const int kbase = split * KPB;              // first k-pair for this block

    // Prologue: plain vector copy of this split's precomputed table (3.5 KB)
    {
        const float4* src = &g_kc[kbase * 7];
        for (int i = threadIdx.x; i < KPB * 7; i += BLK)
            kc[i] = src[i];
    }
    __syncthreads();

    const int p0 = pg * (BLK * NPT) + threadIdx.x;

    u64 xd[NPT], yd[NPT], zd[NPT];
    u64 a0[NPT], axx[NPT], ayy[NPT], azz[NPT];

    #pragma unroll
    for (int i = 0; i < NPT; i++) {
        int n = p0 + i * BLK;
        bool ok = (n < N);
        float xv = ok ? x[n] : 0.0f;
        float yv = ok ? y[n] : 0.0f;
        float zv = ok ? z[n] : 0.0f;
        xd[i] = pk2(xv, xv);
        yd[i] = pk2(yv, yv);
        zd[i] = pk2(zv, zv);
        a0[i] = 0ull; axx[i] = 0ull; ayy[i] = 0ull; azz[i] = 0ull;
    }

    const float NEG_HALF_LOG2E = -0.7213475204444817f;
    const u64 Cd = pk2(NEG_HALF_LOG2E, NEG_HALF_LOG2E);

    for (int kp = 0; kp < KPB; kp++) {
        const ulonglong2* p = reinterpret_cast<const ulonglong2*>(&kc[kp * 7]);
        const ulonglong2 q0 = p[0];   // {wxp, mbx}
        const ulonglong2 q1 = p[1];   // {wyp, mby}
        const ulonglong2 q2 = p[2];   // {wzp, mbz}
        const ulonglong2 q3 = p[3];   // {lcp, sgn}
        const ulonglong2 q4 = p[4];   // {wx2, m3wx2}
        const ulonglong2 q5 = p[5];   // {wy2, m3wy2}
        const ulonglong2 q6 = p[6];   // {wz2, m3wz2}

        #pragma unroll
        for (int i = 0; i < NPT; i++) {
            u64 xt = fma2(xd[i], q0.x, q0.y);
            u64 yt = fma2(yd[i], q1.x, q1.y);
            u64 zt = fma2(zd[i], q2.x, q2.y);

            u64 x2 = mul2(xt, xt);
            u64 y2 = mul2(yt, yt);
            u64 z2 = mul2(zt, zt);

            u64 s   = add2(add2(x2, y2), z2);
            u64 arg = fma2(s, Cd, q3.x);          // s*C + log2|c|

            float alo, ahi;
            upk2(arg, alo, ahi);
            u64 e = pk2(ex2f(alo), ex2f(ahi));

            u64 q  = mul2(mul2(xt, yt), zt);      // xt*yt*zt
            u64 pe = mul2(q, e);
            u64 cp = pe ^ q3.y;                   // sign of -c (ALU pipe)

            a0[i]  = add2(a0[i], cp);
            axx[i] = fma2(cp, fma2(q4.x, x2, q4.y), axx[i]);
            ayy[i] = fma2(cp, fma2(q5.x, y2, q5.y), ayy[i]);
            azz[i] = fma2(cp, fma2(q6.x, z2, q6.y), azz[i]);
        }
    }

    // ---- reduce across splits directly into out via RED.ADD (no return) ----
    #pragma unroll
    for (int i = 0; i < NPT; i++) {
        int n = p0 + i * BLK;
        if (n < N) {
            float lo, hi;
            upk2(a0[i], lo, hi);  atomicAdd(&out[n],         lo + hi);
            upk2(axx[i], lo, hi); atomicAdd(&out[N + n],     lo + hi);
            upk2(ayy[i], lo, hi); atomicAdd(&out[2 * N + n], lo + hi);
            upk2(azz[i], lo, hi); atomicAdd(&out[3 * N + n], lo + hi);
        }
    }
}

extern "C" void kernel_launch(void* const* d_in, const int* in_sizes, int n_in,
                              void* d_out, int out_size)
{
    const float* x     = (const float*)d_in[0];
    const float* y     = (const float*)d_in[1];
    const float* z     = (const float*)d_in[2];
    const float* wx    = (const float*)d_in[3];
    const float* bx    = (const float*)d_in[4];
    const float* wy    = (const float*)d_in[5];
    const float* by    = (const float*)d_in[6];
    const float* wz    = (const float*)d_in[7];
    const float* bz    = (const float*)d_in[8];
    const float* coeff = (const float*)d_in[9];
    const float* bias  = (const float*)d_in[10];
    float* out = (float*)d_out;

    int N = in_sizes[0];
    int nOutBlk = (N + 255) / 256;               // float4-unit blocks for out init
    int pts_per_block = BLK * NPT;
    int pgroups = (N + pts_per_block - 1) / pts_per_block;
    int grid = pgroups * KSPLIT;

    awpinn_init<<<nOutBlk + 1, 256>>>(wx, bx, wy, by, wz, bz, coeff, bias,
                                      (float4*)out, N, nOutBlk);
    awpinn_main<<<grid, BLK>>>(x, y, z, out, N);
}

// round 17
// speedup vs baseline: 1.0433x; 1.0433x over previous
#include <cuda_runtime.h>

#define KW     512
#define KP     (KW / 2)      // k-pairs total
#define KSPLIT 8
#define KPB    (KP / KSPLIT) // k-pairs per block = 32
#define NPT    4             // points per thread
#define BLK    128           // threads per block

typedef unsigned long long u64;

// ---------- packed f32x2 helpers ----------
__device__ __forceinline__ u64 pk2(float lo, float hi) {
    u64 r;
    asm("mov.b64 %0, {%1, %2};" : "=l"(r) : "f"(lo), "f"(hi));
    return r;
}
__device__ __forceinline__ void upk2(u64 v, float& lo, float& hi) {
    asm("mov.b64 {%0, %1}, %2;" : "=f"(lo), "=f"(hi) : "l"(v));
}
__device__ __forceinline__ u64 fma2(u64 a, u64 b, u64 c) {
    u64 d;
    asm("fma.rn.f32x2 %0, %1, %2, %3;" : "=l"(d) : "l"(a), "l"(b), "l"(c));
    return d;
}
__device__ __forceinline__ u64 mul2(u64 a, u64 b) {
    u64 d;
    asm("mul.rn.f32x2 %0, %1, %2;" : "=l"(d) : "l"(a), "l"(b));
    return d;
}
__device__ __forceinline__ u64 add2(u64 a, u64 b) {
    u64 d;
    asm("add.rn.f32x2 %0, %1, %2;" : "=l"(d) : "l"(a), "l"(b));
    return d;
}
__device__ __forceinline__ float ex2f(float a) {
    float r;
    asm("ex2.approx.ftz.f32 %0, %1;" : "=f"(r) : "f"(a));
    return r;
}

// Init: out[0..N) = bias, out[N..4N) = 0, float4 stores (out poisoned before timing)
__global__ __launch_bounds__(256)
void awpinn_init(const float* __restrict__ bias, float4* __restrict__ out, int N)
{
    int j = blockIdx.x * 256 + threadIdx.x;    // float4 units over 4N floats
    int total = N;                              // 4N/4
    int row0  = N >> 2;                         // float4 units in row 0
    if (j < total) {
        float b = (j < row0) ? bias[0] : 0.0f;
        out[j] = make_float4(b, b, b, b);
    }
}

// Per k-pair constants, 7 x 16B (layout per round-3 comment)
__global__ __launch_bounds__(BLK, 4)
void awpinn_main(
    const float* __restrict__ x, const float* __restrict__ y, const float* __restrict__ z,
    const float* __restrict__ wx, const float* __restrict__ bx,
    const float* __restrict__ wy, const float* __restrict__ by,
    const float* __restrict__ wz, const float* __restrict__ bz,
    const float* __restrict__ coeff, float* __restrict__ out, int N, int pgroups)
{
    __shared__ float4 kc[KPB][7];

    // Transposed mapping: same-pg blocks are `pgroups` apart in launch order,
    // so their REDs to shared output addresses arrive staggered in time.
    const int split = blockIdx.x / pgroups;
    const int pg    = blockIdx.x - split * pgroups;
    const int kbase = split * KPB;              // first k-pair for this block

    for (int kp = threadIdx.x; kp < KPB; kp += BLK) {
        int k0 = 2 * (kbase + kp), k1 = k0 + 1;
        float wx0 = wx[k0], wx1 = wx[k1];
        float wy0 = wy[k0], wy1 = wy[k1];
        float wz0 = wz[k0], wz1 = wz[k1];
        float c0 = sqrtf(fmaxf(wx0 * wy0 * wz0, 1e-12f)) * coeff[k0];
        float c1 = sqrtf(fmaxf(wx1 * wy1 * wz1, 1e-12f)) * coeff[k1];
        // cp = (-c)*q*exp2(s*C)  ->  sign(-c) XOR ( q * exp2(s*C + log2|c|) )
        float lc0 = __log2f(fabsf(c0));
        float lc1 = __log2f(fabsf(c1));
        unsigned int sg0 = (c0 > 0.0f) ? 0x80000000u : 0u;
        unsigned int sg1 = (c1 > 0.0f) ? 0x80000000u : 0u;
        float wx20 = wx0 * wx0, wx21 = wx1 * wx1;
        float wy20 = wy0 * wy0, wy21 = wy1 * wy1;
        float wz20 = wz0 * wz0, wz21 = wz1 * wz1;
        kc[kp][0] = make_float4(wx0, wx1, -bx[k0], -bx[k1]);
        kc[kp][1] = make_float4(wy0, wy1, -by[k0], -by[k1]);
        kc[kp][2] = make_float4(wz0, wz1, -bz[k0], -bz[k1]);
        kc[kp][3] = make_float4(lc0, lc1, __uint_as_float(sg0), __uint_as_float(sg1));
        kc[kp][4] = make_float4(wx20, wx21, -3.0f * wx20, -3.0f * wx21);
        kc[kp][5] = make_float4(wy20, wy21, -3.0f * wy20, -3.0f * wy21);
        kc[kp][6] = make_float4(wz20, wz21, -3.0f * wz20, -3.0f * wz21);
    }
    __syncthreads();

    const int p0 = pg * (BLK * NPT) + threadIdx.x;

    u64 xd[NPT], yd[NPT], zd[NPT];
    u64 a0[NPT], axx[NPT], ayy[NPT], azz[NPT];

    #pragma unroll
    for (int i = 0; i < NPT; i++) {
        int n = p0 + i * BLK;
        bool ok = (n < N);
        float xv = ok ? x[n] : 0.0f;
        float yv = ok ? y[n] : 0.0f;
        float zv = ok ? z[n] : 0.0f;
        xd[i] = pk2(xv, xv);
        yd[i] = pk2(yv, yv);
        zd[i] = pk2(zv, zv);
        a0[i] = 0ull; axx[i] = 0ull; ayy[i] = 0ull; azz[i] = 0ull;
    }

    const float NEG_HALF_LOG2E = -0.7213475204444817f;
    const u64 Cd = pk2(NEG_HALF_LOG2E, NEG_HALF_LOG2E);

    #pragma unroll 2
    for (int kp = 0; kp < KPB; kp++) {
        const ulonglong2* p = reinterpret_cast<const ulonglong2*>(&kc[kp][0]);
        const ulonglong2 q0 = p[0];   // {wxp, mbx}
        const ulonglong2 q1 = p[1];   // {wyp, mby}
        const ulonglong2 q2 = p[2];   // {wzp, mbz}
        const ulonglong2 q3 = p[3];   // {lcp, sgn}
        const ulonglong2 q4 = p[4];   // {wx2, m3wx2}
        const ulonglong2 q5 = p[5];   // {wy2, m3wy2}
        const ulonglong2 q6 = p[6];   // {wz2, m3wz2}

        #pragma unroll
        for (int i = 0; i < NPT; i++) {
            u64 xt = fma2(xd[i], q0.x, q0.y);
            u64 yt = fma2(yd[i], q1.x, q1.y);
            u64 zt = fma2(zd[i], q2.x, q2.y);

            u64 x2 = mul2(xt, xt);
            u64 y2 = mul2(yt, yt);
            u64 z2 = mul2(zt, zt);

            u64 s   = add2(add2(x2, y2), z2);
            u64 arg = fma2(s, Cd, q3.x);          // s*C + log2|c|

            float alo, ahi;
            upk2(arg, alo, ahi);
            u64 e = pk2(ex2f(alo), ex2f(ahi));

            u64 q  = mul2(mul2(xt, yt), zt);      // xt*yt*zt
            u64 pe = mul2(q, e);
            u64 cp = pe ^ q3.y;                   // sign of -c (ALU pipe)

            a0[i]  = add2(a0[i], cp);
            axx[i] = fma2(cp, fma2(q4.x, x2, q4.y), axx[i]);
            ayy[i] = fma2(cp, fma2(q5.x, y2, q5.y), ayy[i]);
            azz[i] = fma2(cp, fma2(q6.x, z2, q6.y), azz[i]);
        }
    }

    // ---- reduce across splits directly into out via RED.ADD (no return) ----
    #pragma unroll
    for (int i = 0; i < NPT; i++) {
        int n = p0 + i * BLK;
        if (n < N) {
            float lo, hi;
            upk2(a0[i], lo, hi);  atomicAdd(&out[n],         lo + hi);
            upk2(axx[i], lo, hi); atomicAdd(&out[N + n],     lo + hi);
            upk2(ayy[i], lo, hi); atomicAdd(&out[2 * N + n], lo + hi);
            upk2(azz[i], lo, hi); atomicAdd(&out[3 * N + n], lo + hi);
        }
    }
}

extern "C" void kernel_launch(void* const* d_in, const int* in_sizes, int n_in,
                              void* d_out, int out_size)
{
    const float* x     = (const float*)d_in[0];
    const float* y     = (const float*)d_in[1];
    const float* z     = (const float*)d_in[2];
    const float* wx    = (const float*)d_in[3];
    const float* bx    = (const float*)d_in[4];
    const float* wy    = (const float*)d_in[5];
    const float* by    = (const float*)d_in[6];
    const float* wz    = (const float*)d_in[7];
    const float* bz    = (const float*)d_in[8];
    const float* coeff = (const float*)d_in[9];
    const float* bias  = (const float*)d_in[10];
    float* out = (float*)d_out;

    int N = in_sizes[0];
    int pts_per_block = BLK * NPT;
    int pgroups = (N + pts_per_block - 1) / pts_per_block;
    int grid = pgroups * KSPLIT;

    awpinn_init<<<(N + 255) / 256, 256>>>(bias, (float4*)out, N);
    awpinn_main<<<grid, BLK>>>(x, y, z, wx, bx, wy, by, wz, bz, coeff, out, N, pgroups);
}